// round 13
// baseline (speedup 1.0000x reference)
#include <cuda_runtime.h>
#include <cuda_bf16.h>
#include <cuda_fp16.h>
#include <cuda_fp8.h>
#include <cstdint>
#include <math.h>

#define NB 512
#define SEQ 128
#define D 256
#define NREST 65024            // NB*(SEQ-1)

#define BM 128
#define BROWS 127              // real columns per tile = one batch of rest rows
#define GRIDX 4                // NB/BM
#define GRIDY 74               // persistent: 4*74 = 296 CTAs = 2/SM
#define NTILES NB              // 512 tiles, one per batch
#define TOTAL_BLOCKS (GRIDX * GRIDY)
#define THREADS 288            // 8 consumer warps + 1 producer warp

#define SROW 272               // bytes per smem row: 256 fp8 + 16 pad (conflict-free LDSM)
#define TILE_BYTES (128 * SROW)   // 34816 (includes zero pad row 127)

// dynamic smem layout (bytes)
#define SM_A 0
#define SM_B TILE_BYTES                       // two stages: + (t&1)*TILE_BYTES
#define SM_MBAR (SM_B + 2 * TILE_BYTES)       // full[2], empty[2] : 4 x 8B
#define SM_MISC (SM_MBAR + 64)
#define SM_TOTAL (SM_MISC + 2 * BM * 4 + 64 + 64 * 4)

// ---------------- device scratch ----------------
__device__ uint8_t g_anchors[NB * D];        // e4m3
__device__ uint8_t g_rest[(size_t)NREST * D];
__device__ int   g_labels[NB];
__device__ float g_tot[NB];
__device__ float g_pos[NB];
__device__ unsigned g_done;

__device__ __forceinline__ uint32_t smem_u32(const void* p) {
    return (uint32_t)__cvta_generic_to_shared(p);
}
__device__ __forceinline__ void cp_async16(uint32_t dst, const void* src) {
    asm volatile("cp.async.cg.shared.global [%0], [%1], 16;" :: "r"(dst), "l"(src) : "memory");
}
__device__ __forceinline__ void cp_commit() {
    asm volatile("cp.async.commit_group;" ::: "memory");
}
template <int N>
__device__ __forceinline__ void cp_wait() {
    asm volatile("cp.async.wait_group %0;" :: "n"(N) : "memory");
}
__device__ __forceinline__ void mbar_init(uint32_t a, uint32_t cnt) {
    asm volatile("mbarrier.init.shared.b64 [%0], %1;" :: "r"(a), "r"(cnt) : "memory");
}
__device__ __forceinline__ void mbar_arrive(uint32_t a) {
    asm volatile("mbarrier.arrive.shared.b64 _, [%0];" :: "r"(a) : "memory");
}
__device__ __forceinline__ void cp_async_mbar_arrive(uint32_t a) {
    asm volatile("cp.async.mbarrier.arrive.noinc.shared.b64 [%0];" :: "r"(a) : "memory");
}
__device__ __forceinline__ void mbar_wait(uint32_t a, uint32_t parity) {
    uint32_t done;
    asm volatile("{\n\t.reg .pred p;\n\t"
                 "mbarrier.try_wait.parity.acquire.cta.shared::cta.b64 p, [%1], %2;\n\t"
                 "selp.b32 %0, 1, 0, p;\n\t}" : "=r"(done) : "r"(a), "r"(parity) : "memory");
    while (!done) {
        asm volatile("{\n\t.reg .pred p;\n\t"
                     "mbarrier.try_wait.parity.acquire.cta.shared::cta.b64 p, [%1], %2, 0x989680;\n\t"
                     "selp.b32 %0, 1, 0, p;\n\t}" : "=r"(done) : "r"(a), "r"(parity) : "memory");
    }
}

// ---------------- kernel 1: normalize + init, write e4m3 ----------------
__global__ void normalize_kernel(const float* __restrict__ inp, const int* __restrict__ lab) {
    int gtid = blockIdx.x * 256 + threadIdx.x;
    if (gtid < NB) { g_tot[gtid] = 0.0f; g_pos[gtid] = 0.0f; g_labels[gtid] = lab[gtid]; }
    if (gtid == 0) g_done = 0u;

    int row  = blockIdx.x * 8 + (threadIdx.x >> 5);
    int lane = threadIdx.x & 31;
    const float4* p = reinterpret_cast<const float4*>(inp + (size_t)row * D) + lane * 2;
    float4 a = p[0];
    float4 b = p[1];
    float ss = a.x*a.x + a.y*a.y + a.z*a.z + a.w*a.w
             + b.x*b.x + b.y*b.y + b.z*b.z + b.w*b.w;
    #pragma unroll
    for (int o = 16; o > 0; o >>= 1) ss += __shfl_xor_sync(0xffffffffu, ss, o);
    float scale = 1.0f / fmaxf(sqrtf(ss), 1e-12f);

    int bidx = row >> 7;
    int l    = row & 127;
    uint8_t* dst = (l == 0)
        ? (g_anchors + (size_t)bidx * D)
        : (g_rest + (size_t)(bidx * (SEQ - 1) + (l - 1)) * D);

    __nv_fp8x2_storage_t q0 = __nv_cvt_float2_to_fp8x2(
        make_float2(a.x * scale, a.y * scale), __NV_SATFINITE, __NV_E4M3);
    __nv_fp8x2_storage_t q1 = __nv_cvt_float2_to_fp8x2(
        make_float2(a.z * scale, a.w * scale), __NV_SATFINITE, __NV_E4M3);
    __nv_fp8x2_storage_t q2 = __nv_cvt_float2_to_fp8x2(
        make_float2(b.x * scale, b.y * scale), __NV_SATFINITE, __NV_E4M3);
    __nv_fp8x2_storage_t q3 = __nv_cvt_float2_to_fp8x2(
        make_float2(b.z * scale, b.w * scale), __NV_SATFINITE, __NV_E4M3);
    uint2 u;
    u.x = (uint32_t)q0 | ((uint32_t)q1 << 16);
    u.y = (uint32_t)q2 | ((uint32_t)q3 << 16);
    *reinterpret_cast<uint2*>(dst + lane * 8) = u;
}

// ---------------- kernel 2: warp-specialized persistent FP8 GEMM ----------------
__global__ void __launch_bounds__(THREADS, 2) score_kernel(float* __restrict__ out) {
    extern __shared__ __align__(16) char S[];

    float* sTot  = reinterpret_cast<float*>(S + SM_MISC);
    float* sPos  = sTot + BM;
    int*   sFlag = reinterpret_cast<int*>(sPos + BM);
    int*   sHist = sFlag + 16;

    int tid  = threadIdx.x;
    int lane = tid & 31;
    int warp = tid >> 5;
    int bm = blockIdx.x * BM;
    int gy = blockIdx.y;
    int T  = (NTILES - gy + GRIDY - 1) / GRIDY;   // 7 or 6 tiles (batches)

    if (tid < BM) { sTot[tid] = 0.0f; sPos[tid] = 0.0f; }

    uint32_t smA  = smem_u32(S + SM_A);
    uint32_t smB  = smem_u32(S + SM_B);
    uint32_t FULL = smem_u32(S + SM_MBAR);         // full[st] = FULL + st*8
    uint32_t EMPT = FULL + 16;                     // empty[st] = EMPT + st*8

    if (tid == 0) {
        mbar_init(FULL,      32); mbar_init(FULL + 8,  32);   // producer threads
        mbar_init(EMPT,       8); mbar_init(EMPT + 8,   8);   // consumer warps
    }
    // zero the pad row (row 127) of both B stages once; never overwritten
    if (tid >= 32 && tid < 64) {
        int k = tid - 32;
        int st = k >> 4, c = k & 15;
        *reinterpret_cast<uint4*>(S + SM_B + st * TILE_BYTES + 127 * SROW + c * 16) =
            make_uint4(0u, 0u, 0u, 0u);
    }
    __syncthreads();   // mbarrier init + pad rows visible

    if (warp < 8) {
        // consumers load A (128 rows x 16 chunks = 2048 -> 8/thread)
        const uint8_t* gA = g_anchors + (size_t)bm * D;
        #pragma unroll
        for (int i = 0; i < 8; i++) {
            int idx = tid + i * 256;
            int r = idx >> 4, c = idx & 15;
            cp_async16(smA + r * SROW + c * 16, gA + (size_t)r * D + c * 16);
        }
        cp_commit();
        cp_wait<0>();
    } else {
        // producer: stages 0 and 1
        #pragma unroll 1
        for (int t = 0; t < 2; t++) {
            int j = gy + t * GRIDY;
            const uint8_t* gB = g_rest + (size_t)j * BROWS * D;
            uint32_t dstBase = smB + (t & 1) * TILE_BYTES;
            for (int i = 0; i < 64; i++) {
                int idx = lane + i * 32;
                if (idx < BROWS * 16) {
                    int r = idx >> 4, c = idx & 15;
                    cp_async16(dstBase + r * SROW + c * 16, gB + (size_t)r * D + c * 16);
                }
            }
            cp_async_mbar_arrive(FULL + (t & 1) * 8);
        }
    }
    __syncthreads();   // A visible to all consumer warps

    if (warp == 8) {
        // ---------------- producer loop ----------------
        #pragma unroll 1
        for (int t = 2; t < T; t++) {
            int st = t & 1;
            mbar_wait(EMPT + st * 8, ((t - 2) >> 1) & 1);
            int j = gy + t * GRIDY;
            const uint8_t* gB = g_rest + (size_t)j * BROWS * D;
            uint32_t dstBase = smB + st * TILE_BYTES;
            for (int i = 0; i < 64; i++) {
                int idx = lane + i * 32;
                if (idx < BROWS * 16) {
                    int r = idx >> 4, c = idx & 15;
                    cp_async16(dstBase + r * SROW + c * 16, gB + (size_t)r * D + c * 16);
                }
            }
            cp_async_mbar_arrive(FULL + st * 8);
        }
    } else {
        // ---------------- consumer warps 0-7 ----------------
        int wm = (warp & 3) * 32;   // 4 warps along M
        int wn = (warp >> 2) * 64;  // 2 warps along N
        int qr = lane >> 2;
        int rlab[2][2];
        #pragma unroll
        for (int mf = 0; mf < 2; mf++)
            #pragma unroll
            for (int h = 0; h < 2; h++)
                rlab[mf][h] = g_labels[bm + wm + mf * 16 + h * 8 + qr];

        float rts[2][2] = {{0.f, 0.f}, {0.f, 0.f}};
        float rps[2][2] = {{0.f, 0.f}, {0.f, 0.f}};
        uint32_t afr[2][4], bfr[8][2];
        const float C = 1.4426950408889634f;   // log2(e)

        #pragma unroll 1
        for (int t = 0; t < T; t++) {
            int st = t & 1;
            int jlab = g_labels[gy + t * GRIDY];
            mbar_wait(FULL + st * 8, (t >> 1) & 1);

            uint32_t bBase = smB + st * TILE_BYTES;

            float acc[2][8][4];
            #pragma unroll
            for (int mf = 0; mf < 2; mf++)
                #pragma unroll
                for (int nf = 0; nf < 8; nf++)
                    #pragma unroll
                    for (int r = 0; r < 4; r++) acc[mf][nf][r] = 0.0f;

            #pragma unroll
            for (int ks = 0; ks < 8; ks++) {
                #pragma unroll
                for (int mf = 0; mf < 2; mf++) {
                    uint32_t addr = smA + (wm + mf * 16 + (lane & 15)) * SROW
                                        + ks * 32 + (lane >> 4) * 16;
                    asm volatile("ldmatrix.sync.aligned.m8n8.x4.shared.b16 {%0,%1,%2,%3}, [%4];"
                                 : "=r"(afr[mf][0]), "=r"(afr[mf][1]),
                                   "=r"(afr[mf][2]), "=r"(afr[mf][3])
                                 : "r"(addr));
                }
                #pragma unroll
                for (int np = 0; np < 4; np++) {
                    uint32_t addr = bBase + (wn + np * 16 + (lane >> 4) * 8 + (lane & 7)) * SROW
                                          + ks * 32 + ((lane >> 3) & 1) * 16;
                    asm volatile("ldmatrix.sync.aligned.m8n8.x4.shared.b16 {%0,%1,%2,%3}, [%4];"
                                 : "=r"(bfr[2 * np][0]), "=r"(bfr[2 * np][1]),
                                   "=r"(bfr[2 * np + 1][0]), "=r"(bfr[2 * np + 1][1])
                                 : "r"(addr));
                }
                #pragma unroll
                for (int mf = 0; mf < 2; mf++)
                    #pragma unroll
                    for (int nf = 0; nf < 8; nf++)
                        asm volatile(
                            "mma.sync.aligned.m16n8k32.row.col.f32.e4m3.e4m3.f32 "
                            "{%0,%1,%2,%3}, {%4,%5,%6,%7}, {%8,%9}, {%0,%1,%2,%3};"
                            : "+f"(acc[mf][nf][0]), "+f"(acc[mf][nf][1]),
                              "+f"(acc[mf][nf][2]), "+f"(acc[mf][nf][3])
                            : "r"(afr[mf][0]), "r"(afr[mf][1]), "r"(afr[mf][2]), "r"(afr[mf][3]),
                              "r"(bfr[nf][0]), "r"(bfr[nf][1]));
            }

            // all LDSM reads of this stage are done -> free it for the producer
            if (lane == 0) mbar_arrive(EMPT + st * 8);

            // epilogue: packed f16x2 exp2 + pair-sum; per-thread column share
            #pragma unroll
            for (int mf = 0; mf < 2; mf++) {
                #pragma unroll
                for (int h = 0; h < 2; h++) {
                    __half2 hs = __floats2half2_rn(0.0f, 0.0f);
                    #pragma unroll
                    for (int nf = 0; nf < 8; nf++) {
                        __half2 hx = __floats2half2_rn(acc[mf][nf][h * 2 + 0] * C,
                                                       acc[mf][nf][h * 2 + 1] * C);
                        hs = __hadd2(hs, h2exp2(hx));
                    }
                    float2 f = __half22float2(hs);
                    float ts = f.x + f.y;
                    rts[mf][h] += ts;
                    rps[mf][h] += (jlab == rlab[mf][h]) ? ts : 0.0f;
                }
            }
        }

        // drain: one quad reduction at the end, then smem atomics
        #pragma unroll
        for (int mf = 0; mf < 2; mf++) {
            #pragma unroll
            for (int h = 0; h < 2; h++) {
                float ts = rts[mf][h], ps = rps[mf][h];
                ts += __shfl_xor_sync(0xffffffffu, ts, 1);
                ts += __shfl_xor_sync(0xffffffffu, ts, 2);
                ps += __shfl_xor_sync(0xffffffffu, ps, 1);
                ps += __shfl_xor_sync(0xffffffffu, ps, 2);
                if ((lane & 3) == 0) {
                    int lrow = wm + mf * 16 + h * 8 + qr;
                    atomicAdd(&sTot[lrow], ts);
                    atomicAdd(&sPos[lrow], ps);
                }
            }
        }
    }

    __syncthreads();
    if (tid < BM) {
        atomicAdd(&g_tot[bm + tid], sTot[tid]);
        atomicAdd(&g_pos[bm + tid], sPos[tid]);
    }

    // ---- fused finalize: last CTA computes the loss ----
    __threadfence();
    __syncthreads();
    if (tid == 0) {
        unsigned v = atomicAdd(&g_done, 1u);
        sFlag[0] = (v == TOTAL_BLOCKS - 1) ? 1 : 0;
    }
    __syncthreads();
    if (sFlag[0]) {
        __threadfence();
        // histogram of labels (pad-column correction for pos)
        if (tid < 64) sHist[tid] = 0;
        __syncthreads();
        int l0 = 0, l1 = 0;
        if (tid < 256) {
            l0 = g_labels[tid]; l1 = g_labels[tid + 256];
            atomicAdd(&sHist[l0], 1);
            atomicAdd(&sHist[l1], 1);
        }
        __syncthreads();
        // every tile adds exp(0)=1 to tot; same-label tiles add 1 to pos
        float v = 0.0f;
        if (tid < 256)
            v = (logf(g_tot[tid]       - 512.0f) - logf(g_pos[tid]       - (float)sHist[l0]))
              + (logf(g_tot[tid + 256] - 512.0f) - logf(g_pos[tid + 256] - (float)sHist[l1]));
        #pragma unroll
        for (int o = 16; o > 0; o >>= 1) v += __shfl_xor_sync(0xffffffffu, v, o);
        float* red = sTot;   // reuse
        if (lane == 0 && warp < 8) red[warp] = v;
        __syncthreads();
        if (tid == 0) {
            float s = 0.0f;
            #pragma unroll
            for (int w = 0; w < 8; w++) s += red[w];
            out[0] = s * (1.0f / 512.0f);
        }
    }
}

// ---------------- launch ----------------
extern "C" void kernel_launch(void* const* d_in, const int* in_sizes, int n_in,
                              void* d_out, int out_size) {
    const float* inp = (const float*)d_in[0];
    const int*   lab = (const int*)d_in[1];
    float*       out = (float*)d_out;

    cudaFuncSetAttribute(score_kernel, cudaFuncAttributeMaxDynamicSharedMemorySize, SM_TOTAL);

    normalize_kernel<<<(NB * SEQ) / 8, 256>>>(inp, lab);
    score_kernel<<<dim3(GRIDX, GRIDY), THREADS, SM_TOTAL>>>(out);
}

// round 14
// speedup vs baseline: 1.0297x; 1.0297x over previous
#include <cuda_runtime.h>
#include <cuda_bf16.h>
#include <cuda_fp16.h>
#include <cuda_fp8.h>
#include <cstdint>
#include <math.h>

#define NB 512
#define SEQ 128
#define D 256
#define NREST 65024            // NB*(SEQ-1)

#define BM 256
#define BROWS 127              // real columns per tile = one batch of rest rows
#define GRIDX 2                // NB/BM
#define GRIDY 74               // 2*74 = 148 CTAs = 1/SM
#define NTILES NB              // 512 tiles, one per batch
#define TOTAL_BLOCKS (GRIDX * GRIDY)
#define THREADS 512

#define SROW 272               // bytes per smem row: 256 fp8 + 16 pad (conflict-free LDSM)
#define A_BYTES (BM * SROW)    // 69632
#define TILE_BYTES (128 * SROW)   // 34816 (includes zero pad row 127)

// dynamic smem layout (bytes): A + 3 B stages + misc
#define SM_A 0
#define SM_B A_BYTES
#define SM_MISC (SM_B + 3 * TILE_BYTES)       // 174080
#define SM_TOTAL (SM_MISC + 2 * BM * 4 + 64 + 64 * 4)

// ---------------- device scratch ----------------
__device__ uint8_t g_anchors[NB * D];        // e4m3
__device__ uint8_t g_rest[(size_t)NREST * D];
__device__ int   g_labels[NB];
__device__ float g_tot[NB];
__device__ float g_pos[NB];
__device__ unsigned g_done;

__device__ __forceinline__ uint32_t smem_u32(const void* p) {
    return (uint32_t)__cvta_generic_to_shared(p);
}
__device__ __forceinline__ void cp_async16(uint32_t dst, const void* src) {
    asm volatile("cp.async.cg.shared.global [%0], [%1], 16;" :: "r"(dst), "l"(src) : "memory");
}
__device__ __forceinline__ void cp_commit() {
    asm volatile("cp.async.commit_group;" ::: "memory");
}
template <int N>
__device__ __forceinline__ void cp_wait() {
    asm volatile("cp.async.wait_group %0;" :: "n"(N) : "memory");
}

// ---------------- kernel 1: normalize + init, write e4m3 ----------------
__global__ void normalize_kernel(const float* __restrict__ inp, const int* __restrict__ lab) {
    int gtid = blockIdx.x * 256 + threadIdx.x;
    if (gtid < NB) { g_tot[gtid] = 0.0f; g_pos[gtid] = 0.0f; g_labels[gtid] = lab[gtid]; }
    if (gtid == 0) g_done = 0u;

    int row  = blockIdx.x * 8 + (threadIdx.x >> 5);
    int lane = threadIdx.x & 31;
    const float4* p = reinterpret_cast<const float4*>(inp + (size_t)row * D) + lane * 2;
    float4 a = p[0];
    float4 b = p[1];
    float ss = a.x*a.x + a.y*a.y + a.z*a.z + a.w*a.w
             + b.x*b.x + b.y*b.y + b.z*b.z + b.w*b.w;
    #pragma unroll
    for (int o = 16; o > 0; o >>= 1) ss += __shfl_xor_sync(0xffffffffu, ss, o);
    float scale = 1.0f / fmaxf(sqrtf(ss), 1e-12f);

    int bidx = row >> 7;
    int l    = row & 127;
    uint8_t* dst = (l == 0)
        ? (g_anchors + (size_t)bidx * D)
        : (g_rest + (size_t)(bidx * (SEQ - 1) + (l - 1)) * D);

    __nv_fp8x2_storage_t q0 = __nv_cvt_float2_to_fp8x2(
        make_float2(a.x * scale, a.y * scale), __NV_SATFINITE, __NV_E4M3);
    __nv_fp8x2_storage_t q1 = __nv_cvt_float2_to_fp8x2(
        make_float2(a.z * scale, a.w * scale), __NV_SATFINITE, __NV_E4M3);
    __nv_fp8x2_storage_t q2 = __nv_cvt_float2_to_fp8x2(
        make_float2(b.x * scale, b.y * scale), __NV_SATFINITE, __NV_E4M3);
    __nv_fp8x2_storage_t q3 = __nv_cvt_float2_to_fp8x2(
        make_float2(b.z * scale, b.w * scale), __NV_SATFINITE, __NV_E4M3);
    uint2 u;
    u.x = (uint32_t)q0 | ((uint32_t)q1 << 16);
    u.y = (uint32_t)q2 | ((uint32_t)q3 << 16);
    *reinterpret_cast<uint2*>(dst + lane * 8) = u;
}

// ---------------- kernel 2: 512-thread FP8 GEMM, 3-stage ring, 1 sync/tile ----------
__global__ void __launch_bounds__(THREADS) score_kernel(float* __restrict__ out) {
    extern __shared__ __align__(16) char S[];

    float* sTot  = reinterpret_cast<float*>(S + SM_MISC);
    float* sPos  = sTot + BM;
    int*   sFlag = reinterpret_cast<int*>(sPos + BM);
    int*   sHist = sFlag + 16;

    int tid  = threadIdx.x;
    int lane = tid & 31;
    int warp = tid >> 5;
    int wm = (warp & 3) * 64;   // 4 warp-groups along M (m64 each)
    int wn = (warp >> 2) * 32;  // 4 along N (n32 each)
    int bm = blockIdx.x * BM;
    int gy = blockIdx.y;
    int T  = (NTILES - gy + GRIDY - 1) / GRIDY;   // 7 (gy<68) or 6

    if (tid < BM) { sTot[tid] = 0.0f; sPos[tid] = 0.0f; }

    uint32_t smA = smem_u32(S + SM_A);
    uint32_t smB = smem_u32(S + SM_B);

    // zero pad row (row 127) of all 3 B stages once
    if (tid < 48) {
        int st = tid >> 4, c = tid & 15;
        *reinterpret_cast<uint4*>(S + SM_B + st * TILE_BYTES + 127 * SROW + c * 16) =
            make_uint4(0u, 0u, 0u, 0u);
    }

    // B tile load: 127 rows x 16 chunks = 2032 -> 4/thread
    #define ISSUE_B(t_, st_)                                                        \
        do {                                                                        \
            int _j = gy + (t_) * GRIDY;                                             \
            const uint8_t* _gB = g_rest + (size_t)_j * BROWS * D;                   \
            _Pragma("unroll")                                                       \
            for (int i = 0; i < 4; i++) {                                           \
                int idx = tid + i * THREADS;                                        \
                if (idx < BROWS * 16) {                                             \
                    int r = idx >> 4, c = idx & 15;                                 \
                    cp_async16(smB + (st_) * TILE_BYTES + r * SROW + c * 16,        \
                               _gB + (size_t)r * D + c * 16);                       \
                }                                                                   \
            }                                                                       \
            cp_commit();                                                            \
        } while (0)

    // prologue: A (256 rows x 16 chunks = 4096 -> 8/thread) + B0 in group 0; B1 in group 1
    {
        const uint8_t* gA = g_anchors + (size_t)bm * D;
        #pragma unroll
        for (int i = 0; i < 8; i++) {
            int idx = tid + i * THREADS;
            int r = idx >> 4, c = idx & 15;
            cp_async16(smA + r * SROW + c * 16, gA + (size_t)r * D + c * 16);
        }
    }
    ISSUE_B(0, 0);        // commits group 0 (A + B0)
    ISSUE_B(1, 1);        // group 1

    // row labels fixed per thread (8 rows/thread for m64 warp tile)
    int qr = lane >> 2;
    int rlab[4][2];
    #pragma unroll
    for (int mf = 0; mf < 4; mf++)
        #pragma unroll
        for (int h = 0; h < 2; h++)
            rlab[mf][h] = g_labels[bm + wm + mf * 16 + h * 8 + qr];

    float rts[4][2], rps[4][2];
    #pragma unroll
    for (int mf = 0; mf < 4; mf++)
        #pragma unroll
        for (int h = 0; h < 2; h++) { rts[mf][h] = 0.0f; rps[mf][h] = 0.0f; }

    uint32_t afr[4][4], bfr[4][2];
    const float C = 1.4426950408889634f;   // log2(e)

    #pragma unroll 1
    for (int t = 0; t < T; t++) {
        int jlab = g_labels[gy + t * GRIDY];

        if (t + 1 < T) cp_wait<1>(); else cp_wait<0>();
        __syncthreads();                       // single barrier per tile
        if (t + 2 < T) ISSUE_B(t + 2, (t + 2) % 3);   // stage free since tile t-1

        uint32_t bBase = smB + (t % 3) * TILE_BYTES;

        float acc[4][4][4];
        #pragma unroll
        for (int mf = 0; mf < 4; mf++)
            #pragma unroll
            for (int nf = 0; nf < 4; nf++)
                #pragma unroll
                for (int r = 0; r < 4; r++) acc[mf][nf][r] = 0.0f;

        #pragma unroll
        for (int ks = 0; ks < 8; ks++) {
            #pragma unroll
            for (int mf = 0; mf < 4; mf++) {
                uint32_t addr = smA + (wm + mf * 16 + (lane & 15)) * SROW
                                    + ks * 32 + (lane >> 4) * 16;
                asm volatile("ldmatrix.sync.aligned.m8n8.x4.shared.b16 {%0,%1,%2,%3}, [%4];"
                             : "=r"(afr[mf][0]), "=r"(afr[mf][1]),
                               "=r"(afr[mf][2]), "=r"(afr[mf][3])
                             : "r"(addr));
            }
            #pragma unroll
            for (int np = 0; np < 2; np++) {
                uint32_t addr = bBase + (wn + np * 16 + (lane >> 4) * 8 + (lane & 7)) * SROW
                                      + ks * 32 + ((lane >> 3) & 1) * 16;
                asm volatile("ldmatrix.sync.aligned.m8n8.x4.shared.b16 {%0,%1,%2,%3}, [%4];"
                             : "=r"(bfr[2 * np][0]), "=r"(bfr[2 * np][1]),
                               "=r"(bfr[2 * np + 1][0]), "=r"(bfr[2 * np + 1][1])
                             : "r"(addr));
            }
            #pragma unroll
            for (int mf = 0; mf < 4; mf++)
                #pragma unroll
                for (int nf = 0; nf < 4; nf++)
                    asm volatile(
                        "mma.sync.aligned.m16n8k32.row.col.f32.e4m3.e4m3.f32 "
                        "{%0,%1,%2,%3}, {%4,%5,%6,%7}, {%8,%9}, {%0,%1,%2,%3};"
                        : "+f"(acc[mf][nf][0]), "+f"(acc[mf][nf][1]),
                          "+f"(acc[mf][nf][2]), "+f"(acc[mf][nf][3])
                        : "r"(afr[mf][0]), "r"(afr[mf][1]), "r"(afr[mf][2]), "r"(afr[mf][3]),
                          "r"(bfr[nf][0]), "r"(bfr[nf][1]));
        }

        // epilogue: packed f16x2 exp2; per-thread column share, no barrier
        #pragma unroll
        for (int mf = 0; mf < 4; mf++) {
            #pragma unroll
            for (int h = 0; h < 2; h++) {
                __half2 hs = __floats2half2_rn(0.0f, 0.0f);
                #pragma unroll
                for (int nf = 0; nf < 4; nf++) {
                    __half2 hx = __floats2half2_rn(acc[mf][nf][h * 2 + 0] * C,
                                                   acc[mf][nf][h * 2 + 1] * C);
                    hs = __hadd2(hs, h2exp2(hx));
                }
                float2 f = __half22float2(hs);
                float ts = f.x + f.y;
                rts[mf][h] += ts;
                rps[mf][h] += (jlab == rlab[mf][h]) ? ts : 0.0f;
            }
        }
    }

    // drain: one quad reduction, then smem/global atomics
    #pragma unroll
    for (int mf = 0; mf < 4; mf++) {
        #pragma unroll
        for (int h = 0; h < 2; h++) {
            float ts = rts[mf][h], ps = rps[mf][h];
            ts += __shfl_xor_sync(0xffffffffu, ts, 1);
            ts += __shfl_xor_sync(0xffffffffu, ts, 2);
            ps += __shfl_xor_sync(0xffffffffu, ps, 1);
            ps += __shfl_xor_sync(0xffffffffu, ps, 2);
            if ((lane & 3) == 0) {
                int lrow = wm + mf * 16 + h * 8 + qr;
                atomicAdd(&sTot[lrow], ts);
                atomicAdd(&sPos[lrow], ps);
            }
        }
    }
    __syncthreads();
    if (tid < 256) atomicAdd(&g_tot[bm + tid], sTot[tid]);
    else           atomicAdd(&g_pos[bm + tid - 256], sPos[tid - 256]);

    // ---- fused finalize: last CTA computes the loss ----
    __threadfence();
    __syncthreads();
    if (tid == 0) {
        unsigned v = atomicAdd(&g_done, 1u);
        sFlag[0] = (v == TOTAL_BLOCKS - 1) ? 1 : 0;
    }
    __syncthreads();
    if (sFlag[0]) {
        __threadfence();
        if (tid < 64) sHist[tid] = 0;
        __syncthreads();
        int l0 = g_labels[tid];
        atomicAdd(&sHist[l0], 1);
        __syncthreads();
        // every tile adds exp(0)=1 to tot; same-label tiles add 1 to pos
        float v = logf(g_tot[tid] - 512.0f) - logf(g_pos[tid] - (float)sHist[l0]);
        #pragma unroll
        for (int o = 16; o > 0; o >>= 1) v += __shfl_xor_sync(0xffffffffu, v, o);
        float* red = sTot;   // reuse
        if (lane == 0) red[warp] = v;
        __syncthreads();
        if (tid == 0) {
            float s = 0.0f;
            #pragma unroll
            for (int w = 0; w < 16; w++) s += red[w];
            out[0] = s * (1.0f / 512.0f);
        }
    }
}

// ---------------- launch ----------------
extern "C" void kernel_launch(void* const* d_in, const int* in_sizes, int n_in,
                              void* d_out, int out_size) {
    const float* inp = (const float*)d_in[0];
    const int*   lab = (const int*)d_in[1];
    float*       out = (float*)d_out;

    cudaFuncSetAttribute(score_kernel, cudaFuncAttributeMaxDynamicSharedMemorySize, SM_TOTAL);

    normalize_kernel<<<(NB * SEQ) / 8, 256>>>(inp, lab);
    score_kernel<<<dim3(GRIDX, GRIDY), THREADS, SM_TOTAL>>>(out);
}